// round 2
// baseline (speedup 1.0000x reference)
#include <cuda_runtime.h>
#include <math.h>

#define NTOK   32768
#define D      512
#define NTYPE  26
#define NPER   128
#define NCB    (NTYPE*NPER)   // 3328
#define SSAMP  312
#define TEMP   0.07f
#define EPSV   1e-12f

// ---------------- scratch (static device globals; no runtime alloc) ----------
__device__ __align__(16) float g_xn[NTOK * D];     // normalized x
__device__ __align__(16) float g_se[SSAMP * D];    // normalized sampled emb rows
__device__ float g_esq[NCB];                       // per-code squared norm
__device__ int   g_counts[NTYPE];
__device__ int   g_offsets[NTYPE];
__device__ int   g_cursor[NTYPE];
__device__ int   g_sorted[NTOK];
__device__ int   g_enc[NTOK];
__device__ float g_loss_partial[512];
__device__ float g_row_loss[SSAMP];

// ---------------- small utility kernels --------------------------------------
__global__ void k_init() {
    int t = threadIdx.x;
    if (t < NTYPE) { g_counts[t] = 0; }
}

// normalize x rows -> g_xn ; one warp per row
__global__ void k_l2norm_x(const float* __restrict__ x) {
    int warp = (blockIdx.x * blockDim.x + threadIdx.x) >> 5;
    int lane = threadIdx.x & 31;
    if (warp >= NTOK) return;
    const float4* p = (const float4*)(x + (size_t)warp * D);
    float4 v0 = p[lane], v1 = p[lane + 32], v2 = p[lane + 64], v3 = p[lane + 96];
    float ss = v0.x*v0.x + v0.y*v0.y + v0.z*v0.z + v0.w*v0.w
             + v1.x*v1.x + v1.y*v1.y + v1.z*v1.z + v1.w*v1.w
             + v2.x*v2.x + v2.y*v2.y + v2.z*v2.z + v2.w*v2.w
             + v3.x*v3.x + v3.y*v3.y + v3.z*v3.z + v3.w*v3.w;
    #pragma unroll
    for (int o = 16; o > 0; o >>= 1) ss += __shfl_xor_sync(0xffffffffu, ss, o);
    float inv = 1.0f / fmaxf(sqrtf(ss), EPSV);
    float4* q = (float4*)(g_xn + (size_t)warp * D);
    v0.x*=inv; v0.y*=inv; v0.z*=inv; v0.w*=inv;
    v1.x*=inv; v1.y*=inv; v1.z*=inv; v1.w*=inv;
    v2.x*=inv; v2.y*=inv; v2.z*=inv; v2.w*=inv;
    v3.x*=inv; v3.y*=inv; v3.z*=inv; v3.w*=inv;
    q[lane] = v0; q[lane+32] = v1; q[lane+64] = v2; q[lane+96] = v3;
}

// per-code squared norms ; one warp per codebook row
__global__ void k_esq(const float* __restrict__ emb) {
    int warp = (blockIdx.x * blockDim.x + threadIdx.x) >> 5;
    int lane = threadIdx.x & 31;
    if (warp >= NCB) return;
    const float4* p = (const float4*)(emb + (size_t)warp * D);
    float ss = 0.0f;
    #pragma unroll
    for (int i = 0; i < 4; i++) {
        float4 v = p[lane + 32*i];
        ss += v.x*v.x + v.y*v.y + v.z*v.z + v.w*v.w;
    }
    #pragma unroll
    for (int o = 16; o > 0; o >>= 1) ss += __shfl_xor_sync(0xffffffffu, ss, o);
    if (lane == 0) g_esq[warp] = ss;
}

// gather + normalize sampled emb rows -> g_se ; one warp per sampled row
__global__ void k_se(const float* __restrict__ emb, const int* __restrict__ si) {
    int warp = (blockIdx.x * blockDim.x + threadIdx.x) >> 5;
    int lane = threadIdx.x & 31;
    if (warp >= SSAMP) return;
    int src = si[warp];
    const float4* p = (const float4*)(emb + (size_t)src * D);
    float4 v[4];
    float ss = 0.0f;
    #pragma unroll
    for (int i = 0; i < 4; i++) {
        v[i] = p[lane + 32*i];
        ss += v[i].x*v[i].x + v[i].y*v[i].y + v[i].z*v[i].z + v[i].w*v[i].w;
    }
    #pragma unroll
    for (int o = 16; o > 0; o >>= 1) ss += __shfl_xor_sync(0xffffffffu, ss, o);
    float inv = 1.0f / fmaxf(sqrtf(ss), EPSV);
    float4* q = (float4*)(g_se + (size_t)warp * D);
    #pragma unroll
    for (int i = 0; i < 4; i++) {
        float4 w = v[i];
        w.x*=inv; w.y*=inv; w.z*=inv; w.w*=inv;
        q[lane + 32*i] = w;
    }
}

// block-local histogram -> few global atomics
__global__ void k_hist(const int* __restrict__ Q) {
    __shared__ int sc[NTYPE];
    int tid = threadIdx.x;
    if (tid < NTYPE) sc[tid] = 0;
    __syncthreads();
    int n = blockIdx.x * blockDim.x + tid;
    atomicAdd(&sc[Q[n]], 1);
    __syncthreads();
    if (tid < NTYPE && sc[tid] > 0) atomicAdd(&g_counts[tid], sc[tid]);
}

__global__ void k_scan() {
    if (threadIdx.x == 0) {
        int acc = 0;
        for (int i = 0; i < NTYPE; i++) {
            g_offsets[i] = acc;
            g_cursor[i]  = acc;
            acc += g_counts[i];
        }
    }
}

// block-local rank + per-type chunk reservation (order across blocks is
// nondeterministic, but g_enc[tok] is order-invariant, so outputs are stable)
__global__ void k_scatter(const int* __restrict__ Q) {
    __shared__ int sc[NTYPE];
    __shared__ int sbase[NTYPE];
    int tid = threadIdx.x;
    if (tid < NTYPE) sc[tid] = 0;
    __syncthreads();
    int n = blockIdx.x * blockDim.x + tid;
    int t = Q[n];
    int lrank = atomicAdd(&sc[t], 1);
    __syncthreads();
    if (tid < NTYPE && sc[tid] > 0) sbase[tid] = atomicAdd(&g_cursor[tid], sc[tid]);
    __syncthreads();
    g_sorted[sbase[t] + lrank] = n;
}

// ---------------- GEMM (128x128x512 fp32) + per-token argmin -----------------
// Thread tile: 2x2 sub-tiles of 4 (rows ty*4 & 64+ty*4, cols tx*4 & 64+tx*4)
// so fragment reads are conflict-free LDS.128.
__global__ __launch_bounds__(256) void k_gemm_argmin(const float* __restrict__ emb) {
    const int type  = blockIdx.y;
    const int count = g_counts[type];
    const int mbase = blockIdx.x * 128;
    if (mbase >= count) return;
    const int start = g_offsets[type];

    __shared__ float As[16][128];
    __shared__ float Bs[16][128];
    __shared__ int   s_tok[128];
    __shared__ float s_esq[128];

    const int tid = threadIdx.x;
    if (tid < 128) {
        int r = mbase + tid;
        s_tok[tid] = (r < count) ? g_sorted[start + r] : -1;
        s_esq[tid] = g_esq[type * 128 + tid];
    }
    __syncthreads();

    const float* Bbase = emb + (size_t)type * 128 * D;
    float acc[8][8];
    #pragma unroll
    for (int i = 0; i < 8; i++)
        #pragma unroll
        for (int j = 0; j < 8; j++) acc[i][j] = 0.0f;

    const int ty = tid >> 4, tx = tid & 15;

    for (int k0 = 0; k0 < D; k0 += 16) {
        #pragma unroll
        for (int i = 0; i < 2; i++) {
            int s   = tid + i * 256;        // 0..511
            int row = s >> 2;
            int kq  = (s & 3) << 2;
            int tok = s_tok[row];
            float4 a = make_float4(0.f, 0.f, 0.f, 0.f);
            if (tok >= 0) a = *(const float4*)(g_xn + (size_t)tok * D + k0 + kq);
            As[kq+0][row] = a.x; As[kq+1][row] = a.y;
            As[kq+2][row] = a.z; As[kq+3][row] = a.w;
            float4 b = *(const float4*)(Bbase + (size_t)row * D + k0 + kq);
            Bs[kq+0][row] = b.x; Bs[kq+1][row] = b.y;
            Bs[kq+2][row] = b.z; Bs[kq+3][row] = b.w;
        }
        __syncthreads();
        #pragma unroll
        for (int k = 0; k < 16; k++) {
            float4 a0 = *(const float4*)&As[k][ty*4];
            float4 a1 = *(const float4*)&As[k][64 + ty*4];
            float4 b0 = *(const float4*)&Bs[k][tx*4];
            float4 b1 = *(const float4*)&Bs[k][64 + tx*4];
            float ar[8] = {a0.x,a0.y,a0.z,a0.w, a1.x,a1.y,a1.z,a1.w};
            float br[8] = {b0.x,b0.y,b0.z,b0.w, b1.x,b1.y,b1.z,b1.w};
            #pragma unroll
            for (int i = 0; i < 8; i++)
                #pragma unroll
                for (int j = 0; j < 8; j++)
                    acc[i][j] = fmaf(ar[i], br[j], acc[i][j]);
        }
        __syncthreads();
    }

    // argmin epilogue: dist = e_sq[code] - 2*dot (row-constant ||xn||^2 dropped)
    float* rv = &As[0][0];          // reuse smem: 128*16 floats
    int*   ri = (int*)&Bs[0][0];
    #pragma unroll
    for (int i = 0; i < 8; i++) {
        int row = (i < 4) ? (ty*4 + i) : (64 + ty*4 + i - 4);
        float bv = 3.0e38f; int bj = 0;
        #pragma unroll
        for (int j = 0; j < 8; j++) {
            int code = (j < 4) ? (tx*4 + j) : (64 + tx*4 + j - 4);  // ascending in j
            float dist = s_esq[code] - 2.0f * acc[i][j];
            if (dist < bv) { bv = dist; bj = code; }   // strict < keeps first-min
        }
        rv[row*16 + tx] = bv;
        ri[row*16 + tx] = bj;
    }
    __syncthreads();
    if (tid < 128) {
        int tok = s_tok[tid];
        if (tok >= 0) {
            float bv = rv[tid*16]; int bj = ri[tid*16];
            #pragma unroll
            for (int t = 1; t < 16; t++) {
                float v = rv[tid*16 + t];
                int   c = ri[tid*16 + t];
                if (v < bv || (v == bv && c < bj)) { bv = v; bj = c; }
            }
            g_enc[tok] = type * 128 + bj;
        }
    }
}

// ---------------- contrastive (uniform) loss: one block per sampled row ------
__global__ void k_contrastive(const int* __restrict__ si) {
    const int i = blockIdx.x;
    __shared__ float4 sei[D/4];
    const int tid = threadIdx.x;
    const float4* rowp = (const float4*)(g_se + (size_t)i * D);
    for (int q = tid; q < D/4; q += 256) sei[q] = rowp[q];
    __syncthreads();

    const int li = si[i] >> 7;   // label = index / 128
    float sum = 0.0f, pos = 0.0f;
    for (int j = tid; j < SSAMP; j += 256) {
        const float4* pj = (const float4*)(g_se + (size_t)j * D);
        float dot = 0.0f;
        #pragma unroll 8
        for (int q = 0; q < D/4; q++) {
            float4 a = sei[q];
            float4 b = pj[q];
            dot += a.x*b.x + a.y*b.y + a.z*b.z + a.w*b.w;
        }
        if (j != i) {
            float e = expf(dot * (1.0f / TEMP));
            sum += e;
            if ((si[j] >> 7) == li) pos += e;
        }
    }
    __shared__ float rs[256], rp[256];
    rs[tid] = sum; rp[tid] = pos;
    __syncthreads();
    for (int s = 128; s > 0; s >>= 1) {
        if (tid < s) { rs[tid] += rs[tid + s]; rp[tid] += rp[tid + s]; }
        __syncthreads();
    }
    if (tid == 0) g_row_loss[i] = logf(rs[0]) - logf(rp[0]);
}

// ---------------- gather + normalize quantized, MSE partials, index out ------
__global__ void k_output(const float* __restrict__ emb, float* __restrict__ out) {
    const int tid  = threadIdx.x;
    const int base = blockIdx.x * 64;     // tokens per block
    float local = 0.0f;
    #pragma unroll 4
    for (int it = 0; it < 32; it++) {
        int e4 = it * 256 + tid;
        int n  = base + (e4 >> 7);
        int d4 = e4 & 127;
        int idx = g_enc[n];
        float inv = 1.0f / fmaxf(sqrtf(g_esq[idx]), EPSV);
        float4 ev = ((const float4*)(emb + (size_t)idx * D))[d4];
        float4 xv = ((const float4*)(g_xn + (size_t)n * D))[d4];
        float4 q;
        q.x = ev.x * inv; q.y = ev.y * inv; q.z = ev.z * inv; q.w = ev.w * inv;
        ((float4*)out)[(size_t)n * 128 + d4] = q;
        float dx = q.x - xv.x, dy = q.y - xv.y, dz = q.z - xv.z, dw = q.w - xv.w;
        local += dx*dx + dy*dy + dz*dz + dw*dw;
    }
    if (tid < 64) {
        int n = base + tid;
        out[(size_t)NTOK * D + 2 + n] = (float)g_enc[n];
    }
    __shared__ float r[256];
    r[tid] = local;
    __syncthreads();
    for (int s = 128; s > 0; s >>= 1) {
        if (tid < s) r[tid] += r[tid + s];
        __syncthreads();
    }
    if (tid == 0) g_loss_partial[blockIdx.x] = r[0];
}

// ---------------- deterministic scalar finalize ------------------------------
__global__ void k_finalize(float* __restrict__ out) {
    __shared__ float r[512];
    const int tid = threadIdx.x;
    r[tid] = g_loss_partial[tid];
    __syncthreads();
    for (int s = 256; s > 0; s >>= 1) {
        if (tid < s) r[tid] += r[tid + s];
        __syncthreads();
    }
    if (tid == 0)
        out[(size_t)NTOK * D] = 1.25f * r[0] / (float)((size_t)NTOK * D);
    __syncthreads();
    r[tid] = (tid < SSAMP) ? g_row_loss[tid] : 0.0f;
    __syncthreads();
    for (int s = 256; s > 0; s >>= 1) {
        if (tid < s) r[tid] += r[tid + s];
        __syncthreads();
    }
    if (tid == 0)
        out[(size_t)NTOK * D + 1] = r[0] / (float)SSAMP;
}

// ---------------- launch -----------------------------------------------------
extern "C" void kernel_launch(void* const* d_in, const int* in_sizes, int n_in,
                              void* d_out, int out_size) {
    const float* x   = (const float*)d_in[0];
    const int*   Q   = (const int*)  d_in[1];
    const float* emb = (const float*)d_in[2];
    const int*   si  = (const int*)  d_in[3];
    float* out = (float*)d_out;
    (void)in_sizes; (void)n_in; (void)out_size;

    k_init<<<1, 32>>>();
    k_l2norm_x<<<(NTOK * 32) / 256, 256>>>(x);
    k_esq<<<(NCB * 32 + 255) / 256, 256>>>(emb);
    k_hist<<<NTOK / 256, 256>>>(Q);
    k_scan<<<1, 32>>>();
    k_scatter<<<NTOK / 256, 256>>>(Q);
    k_gemm_argmin<<<dim3(32, NTYPE), 256>>>(emb);
    k_se<<<(SSAMP * 32 + 255) / 256, 256>>>(emb, si);
    k_contrastive<<<SSAMP, 256>>>(si);
    k_output<<<NTOK / 64, 256>>>(emb, out);
    k_finalize<<<1, 512>>>(out);
}

// round 3
// speedup vs baseline: 1.0664x; 1.0664x over previous
#include <cuda_runtime.h>
#include <math.h>

#define NTOK   32768
#define D      512
#define NTYPE  26
#define NPER   128
#define NCB    (NTYPE*NPER)   // 3328
#define SSAMP  312
#define TEMP   0.07f
#define EPSV   1e-12f

// ---------------- scratch (static device globals; no runtime alloc) ----------
__device__ __align__(16) float g_se[SSAMP * D];    // normalized sampled emb rows
__device__ float g_esq[NCB];                       // per-code squared norm
__device__ int   g_counts[NTYPE];
__device__ int   g_offsets[NTYPE];
__device__ int   g_cursor[NTYPE];
__device__ int   g_sorted[NTOK];
__device__ int   g_enc[NTOK];
__device__ float g_bd[NTOK];                       // per-token best q.xn dot
__device__ float g_row_loss[SSAMP];

// ---------------- f32x2 packed helpers ---------------------------------------
__device__ __forceinline__ unsigned long long splat2(float a) {
    unsigned long long r;
    asm("mov.b64 %0, {%1, %1};" : "=l"(r) : "f"(a));
    return r;
}
__device__ __forceinline__ void fma2(unsigned long long& d,
                                     unsigned long long a, unsigned long long b) {
    asm("fma.rn.f32x2 %0, %1, %2, %0;" : "+l"(d) : "l"(a), "l"(b));
}
__device__ __forceinline__ float2 unpack2(unsigned long long v) {
    float2 r;
    asm("mov.b64 {%0, %1}, %2;" : "=f"(r.x), "=f"(r.y) : "l"(v));
    return r;
}

// ---------------- hist + scan (one block) -------------------------------------
__global__ __launch_bounds__(1024) void k_histscan(const int* __restrict__ Q) {
    __shared__ int sh[32][33];    // per-warp sub-histograms (padded)
    __shared__ int stot[NTYPE];
    int tid = threadIdx.x, w = tid >> 5;
    for (int i = tid; i < 32 * 33; i += 1024) ((int*)sh)[i] = 0;
    __syncthreads();
    for (int n = tid; n < NTOK; n += 1024) atomicAdd(&sh[w][Q[n]], 1);
    __syncthreads();
    if (tid < NTYPE) {
        int s = 0;
        #pragma unroll
        for (int w2 = 0; w2 < 32; w2++) s += sh[w2][tid];
        g_counts[tid] = s;
        stot[tid] = s;
    }
    __syncthreads();
    if (tid == 0) {
        int acc = 0;
        for (int i = 0; i < NTYPE; i++) {
            g_offsets[i] = acc;
            g_cursor[i]  = acc;
            acc += stot[i];
        }
    }
}

// block-local rank + per-type chunk reservation
__global__ void k_scatter(const int* __restrict__ Q) {
    __shared__ int sc[NTYPE];
    __shared__ int sbase[NTYPE];
    int tid = threadIdx.x;
    if (tid < NTYPE) sc[tid] = 0;
    __syncthreads();
    int n = blockIdx.x * blockDim.x + tid;
    int t = Q[n];
    int lrank = atomicAdd(&sc[t], 1);
    __syncthreads();
    if (tid < NTYPE && sc[tid] > 0) sbase[tid] = atomicAdd(&g_cursor[tid], sc[tid]);
    __syncthreads();
    g_sorted[sbase[t] + lrank] = n;
}

// ---------------- e_sq for all codes + normalized sampled rows (merged) -------
__global__ void k_esq_se(const float* __restrict__ emb, const int* __restrict__ si) {
    int gw  = (blockIdx.x * blockDim.x + threadIdx.x) >> 5;
    int lane = threadIdx.x & 31;
    if (gw < NCB) {
        const float4* p = (const float4*)(emb + (size_t)gw * D);
        float ss = 0.0f;
        #pragma unroll
        for (int i = 0; i < 4; i++) {
            float4 v = p[lane + 32*i];
            ss += v.x*v.x + v.y*v.y + v.z*v.z + v.w*v.w;
        }
        #pragma unroll
        for (int o = 16; o > 0; o >>= 1) ss += __shfl_xor_sync(0xffffffffu, ss, o);
        if (lane == 0) g_esq[gw] = ss;
    } else if (gw < NCB + SSAMP) {
        int r = gw - NCB;
        int src = si[r];
        const float4* p = (const float4*)(emb + (size_t)src * D);
        float4 v[4];
        float ss = 0.0f;
        #pragma unroll
        for (int i = 0; i < 4; i++) {
            v[i] = p[lane + 32*i];
            ss += v[i].x*v[i].x + v[i].y*v[i].y + v[i].z*v[i].z + v[i].w*v[i].w;
        }
        #pragma unroll
        for (int o = 16; o > 0; o >>= 1) ss += __shfl_xor_sync(0xffffffffu, ss, o);
        float inv = 1.0f / fmaxf(sqrtf(ss), EPSV);
        float4* q = (float4*)(g_se + (size_t)r * D);
        #pragma unroll
        for (int i = 0; i < 4; i++) {
            float4 w = v[i];
            w.x*=inv; w.y*=inv; w.z*=inv; w.w*=inv;
            q[lane + 32*i] = w;
        }
    }
}

// ---------------- GEMM (raw x, FFMA2) + fused norm + argmin -------------------
__global__ __launch_bounds__(256, 2) void k_gemm_argmin(const float* __restrict__ x,
                                                        const float* __restrict__ emb) {
    const int type  = blockIdx.y;
    const int count = g_counts[type];
    const int mbase = blockIdx.x * 128;
    if (mbase >= count) return;
    const int start = g_offsets[type];

    __shared__ float As[16][128];
    __shared__ float Bs[16][128];
    __shared__ int   s_tok[128];
    __shared__ float s_esq[128];
    __shared__ float s_ss[128][4];
    __shared__ float s_ainv[128];

    const int tid = threadIdx.x;
    if (tid < 128) {
        int r = mbase + tid;
        s_tok[tid] = (r < count) ? g_sorted[start + r] : -1;
        s_esq[tid] = g_esq[type * 128 + tid];
    }
    __syncthreads();

    const float* Bbase = emb + (size_t)type * 128 * D;

    unsigned long long acc2[8][4];
    #pragma unroll
    for (int i = 0; i < 8; i++)
        #pragma unroll
        for (int p = 0; p < 4; p++) acc2[i][p] = 0ull;

    const int ty = tid >> 4, tx = tid & 15;
    // staging rows for this thread are fixed: row0 = tid>>2, row1 = 64 + tid>>2
    float ss0 = 0.0f, ss1 = 0.0f;

    for (int k0 = 0; k0 < D; k0 += 16) {
        #pragma unroll
        for (int i = 0; i < 2; i++) {
            int s   = tid + i * 256;        // 0..511
            int row = s >> 2;
            int kq  = (s & 3) << 2;
            int tok = s_tok[row];
            float4 a = make_float4(0.f, 0.f, 0.f, 0.f);
            if (tok >= 0) a = *(const float4*)(x + (size_t)tok * D + k0 + kq);
            float pq = a.x*a.x + a.y*a.y + a.z*a.z + a.w*a.w;
            if (i == 0) ss0 += pq; else ss1 += pq;
            As[kq+0][row] = a.x; As[kq+1][row] = a.y;
            As[kq+2][row] = a.z; As[kq+3][row] = a.w;
            float4 b = *(const float4*)(Bbase + (size_t)row * D + k0 + kq);
            Bs[kq+0][row] = b.x; Bs[kq+1][row] = b.y;
            Bs[kq+2][row] = b.z; Bs[kq+3][row] = b.w;
        }
        __syncthreads();
        #pragma unroll
        for (int k = 0; k < 16; k++) {
            float4 a0 = *(const float4*)&As[k][ty*4];
            float4 a1 = *(const float4*)&As[k][64 + ty*4];
            ulonglong2 b01 = *(const ulonglong2*)&Bs[k][tx*4];
            ulonglong2 b23 = *(const ulonglong2*)&Bs[k][64 + tx*4];
            unsigned long long as2[8];
            as2[0] = splat2(a0.x); as2[1] = splat2(a0.y);
            as2[2] = splat2(a0.z); as2[3] = splat2(a0.w);
            as2[4] = splat2(a1.x); as2[5] = splat2(a1.y);
            as2[6] = splat2(a1.z); as2[7] = splat2(a1.w);
            unsigned long long bs2[4] = {b01.x, b01.y, b23.x, b23.y};
            #pragma unroll
            for (int i = 0; i < 8; i++)
                #pragma unroll
                for (int p = 0; p < 4; p++)
                    fma2(acc2[i][p], as2[i], bs2[p]);
        }
        __syncthreads();
    }

    // finish per-row ||x||^2 -> inverse norms
    s_ss[tid >> 2][tid & 3]        = ss0;   // rows 0..63
    s_ss[64 + (tid >> 2)][tid & 3] = ss1;   // rows 64..127
    __syncthreads();
    if (tid < 128) {
        float t = s_ss[tid][0] + s_ss[tid][1] + s_ss[tid][2] + s_ss[tid][3];
        s_ainv[tid] = 1.0f / fmaxf(sqrtf(t), EPSV);
    }
    __syncthreads();

    // argmin epilogue: dist = e_sq[code] - 2*inv_row*rawdot
    float* rv = &As[0][0];
    int*   ri = (int*)&Bs[0][0];
    #pragma unroll
    for (int i = 0; i < 8; i++) {
        int row = (i < 4) ? (ty*4 + i) : (64 + ty*4 + i - 4);
        float inv = s_ainv[row];
        float bv = 3.0e38f; int bj = 0;
        #pragma unroll
        for (int p = 0; p < 4; p++) {
            int cbase = (p < 2) ? (tx*4 + p*2) : (64 + tx*4 + (p-2)*2);
            float2 d = unpack2(acc2[i][p]);
            float d0 = s_esq[cbase]     - 2.0f * inv * d.x;
            float d1 = s_esq[cbase + 1] - 2.0f * inv * d.y;
            if (d0 < bv) { bv = d0; bj = cbase; }      // ascending code order
            if (d1 < bv) { bv = d1; bj = cbase + 1; }
        }
        rv[row*16 + tx] = bv;
        ri[row*16 + tx] = bj;
    }
    __syncthreads();
    if (tid < 128) {
        int tok = s_tok[tid];
        if (tok >= 0) {
            float bv = rv[tid*16]; int bj = ri[tid*16];
            #pragma unroll
            for (int t = 1; t < 16; t++) {
                float v = rv[tid*16 + t];
                int   c = ri[tid*16 + t];
                if (v < bv || (v == bv && c < bj)) { bv = v; bj = c; }
            }
            g_enc[tok] = type * 128 + bj;
            // q . xn = inv * dot * rsqrt(e_sq); inv*dot = (e_sq - dist)/2
            float es = s_esq[bj];
            g_bd[tok] = 0.5f * (es - bv) * rsqrtf(es);
        }
    }
}

// ---------------- contrastive loss: 39 blocks, warp-per-row, staged chunks ----
__global__ __launch_bounds__(256) void k_contrastive(const int* __restrict__ si) {
    __shared__ float sj[8 * 512];   // 8 j-rows per chunk
    __shared__ int   slab[8];
    const int tid = threadIdx.x, w = tid >> 5, lane = tid & 31;
    const int i = blockIdx.x * 8 + w;           // 39*8 = 312 exactly

    float myr[16];
    const float* rowi = g_se + (size_t)i * D;
    #pragma unroll
    for (int t = 0; t < 16; t++) myr[t] = rowi[lane + 32*t];
    const int li = si[i] >> 7;

    float sum = 0.0f, pos = 0.0f;
    for (int c = 0; c < SSAMP / 8; c++) {
        __syncthreads();
        const float4* src = (const float4*)(g_se + (size_t)c * 8 * D);
        float4* dst = (float4*)sj;
        #pragma unroll
        for (int t = 0; t < 4; t++) dst[tid + 256*t] = src[tid + 256*t];
        if (tid < 8) slab[tid] = si[c*8 + tid] >> 7;
        __syncthreads();
        #pragma unroll
        for (int jj = 0; jj < 8; jj++) {
            int j = c*8 + jj;
            const float* pr = sj + jj * 512;
            float d = 0.0f;
            #pragma unroll
            for (int t = 0; t < 16; t++) d = fmaf(myr[t], pr[lane + 32*t], d);
            #pragma unroll
            for (int o = 16; o > 0; o >>= 1) d += __shfl_xor_sync(0xffffffffu, d, o);
            if (j != i) {
                float e = expf(d * (1.0f / TEMP));
                sum += e;
                if (slab[jj] == li) pos += e;
            }
        }
    }
    if (lane == 0) g_row_loss[i] = logf(sum) - logf(pos);
}

// ---------------- gather + normalize quantized + index tail -------------------
__global__ __launch_bounds__(256) void k_output(const float* __restrict__ emb,
                                                float* __restrict__ out) {
    __shared__ float s_inv[64];
    __shared__ int   s_idx[64];
    const int tid  = threadIdx.x;
    const int base = blockIdx.x * 64;
    if (tid < 64) {
        int idx = g_enc[base + tid];
        s_idx[tid] = idx;
        s_inv[tid] = 1.0f / fmaxf(sqrtf(g_esq[idx]), EPSV);
        out[(size_t)NTOK * D + 2 + base + tid] = (float)idx;
    }
    __syncthreads();
    #pragma unroll 4
    for (int it = 0; it < 32; it++) {
        int e4 = it * 256 + tid;
        int r  = e4 >> 7;           // local token 0..63
        int d4 = e4 & 127;
        int idx = s_idx[r];
        float inv = s_inv[r];
        float4 ev = ((const float4*)(emb + (size_t)idx * D))[d4];
        float4 q;
        q.x = ev.x * inv; q.y = ev.y * inv; q.z = ev.z * inv; q.w = ev.w * inv;
        ((float4*)out)[(size_t)(base + r) * 128 + d4] = q;
    }
}

// ---------------- deterministic scalar finalize -------------------------------
__global__ __launch_bounds__(1024) void k_finalize(float* __restrict__ out) {
    __shared__ float r[1024];
    const int tid = threadIdx.x;
    float s = 0.0f;
    for (int n = tid; n < NTOK; n += 1024) s += g_bd[n];
    r[tid] = s;
    __syncthreads();
    for (int st = 512; st > 0; st >>= 1) {
        if (tid < st) r[tid] += r[tid + st];
        __syncthreads();
    }
    if (tid == 0)
        out[(size_t)NTOK * D] = 2.5f * ((float)NTOK - r[0]) / (float)((size_t)NTOK * D);
    __syncthreads();
    r[tid] = (tid < SSAMP) ? g_row_loss[tid] : 0.0f;
    __syncthreads();
    for (int st = 512; st > 0; st >>= 1) {
        if (tid < st) r[tid] += r[tid + st];
        __syncthreads();
    }
    if (tid == 0)
        out[(size_t)NTOK * D + 1] = r[0] / (float)SSAMP;
}

// ---------------- launch -----------------------------------------------------
extern "C" void kernel_launch(void* const* d_in, const int* in_sizes, int n_in,
                              void* d_out, int out_size) {
    const float* x   = (const float*)d_in[0];
    const int*   Q   = (const int*)  d_in[1];
    const float* emb = (const float*)d_in[2];
    const int*   si  = (const int*)  d_in[3];
    float* out = (float*)d_out;
    (void)in_sizes; (void)n_in; (void)out_size;

    k_esq_se<<<(NCB + SSAMP + 7) / 8, 256>>>(emb, si);
    k_histscan<<<1, 1024>>>(Q);
    k_scatter<<<NTOK / 256, 256>>>(Q);
    k_gemm_argmin<<<dim3(16, NTYPE), 256>>>(x, emb);
    k_contrastive<<<SSAMP / 8, 256>>>(si);
    k_output<<<NTOK / 64, 256>>>(emb, out);
    k_finalize<<<1, 1024>>>(out);
}